// round 14
// baseline (speedup 1.0000x reference)
#include <cuda_runtime.h>
#include <cstdint>

// ---------------------------------------------------------------------------
// Batched greedy nearest-neighbor (B=64, N=1000).
// prep:  per-batch visited bitmap (ballot), C, clamped start, dtype detect.
// build: one warp per reachable row; 8 asm-batched LDG.128.cs (MLP=8), exact
//        top-16 cols in (sortable-f32,col) order via per-lane top-2 cache +
//        16x(REDUX,REDUX) extraction. __launch_bounds__(256,3).
// chain: prefix in SMEM, visited bitmap in warp registers; step = LDS +
//        SHFL + BALLOT/FFS + SHFL; prefix-exhausted -> exact full-row scan.
// Non-conforming shapes -> proven direct-f32 chain.
// ---------------------------------------------------------------------------

#define MK_BYTE  0
#define MK_WORD  1
#define MK_DWORD 2
#define MK_HALF  3

#define SK_I32 0
#define SK_I64 1
#define SK_F32 2

#define K_PREF 16
#define MAXB   65536

__device__ int g_mask_kind, g_start_kind, g_pad;
__device__ unsigned short g_prefix[16777216];      // 32MB (<=1M rows)
__device__ unsigned int   g_bitmap[MAXB * 32];     // 8MB  per-batch visited
__device__ int            g_startc[MAXB];
__device__ int            g_C[MAXB];

__device__ __forceinline__ bool mask_at(const void* mask, int mk, int off) {
    if (mk == MK_WORD)  return ((const unsigned int*)mask)[off]      != 0u;
    if (mk == MK_BYTE)  return ((const unsigned char*)mask)[off]     != 0u;
    if (mk == MK_HALF)  return ((const unsigned short*)mask)[off]    != 0u;
    return ((const unsigned int*)mask)[2 * off] != 0u;                 // i64
}

__device__ __forceinline__ int read_start_k(const void* start_idx, int sk, int b) {
    const int* s32 = (const int*)start_idx;
    if (sk == SK_I64) return s32[2 * b];
    if (sk == SK_F32) return (int)((const float*)start_idx)[b];
    return s32[b];
}

__device__ __forceinline__ unsigned int sortable(float f) {
    unsigned int fb = __float_as_uint(f);
    return fb ^ ((((int)fb) >> 31) | 0x80000000u);
}

__device__ __forceinline__ float4 ldg128_cs(const float* p) {
    float4 v;
    asm volatile("ld.global.cs.v4.f32 {%0,%1,%2,%3}, [%4];"
                 : "=f"(v.x), "=f"(v.y), "=f"(v.z), "=f"(v.w)
                 : "l"(p));
    return v;
}

// detection core, shared by prep (per-CTA) and detect_kernel
__device__ void detect_core(const unsigned int* mw, int m_nwords,
                            const unsigned int* sw, int s_nwords,
                            const unsigned int* pw, int has_pad, int N,
                            int* out_mk, int* out_sk, int* out_pad,
                            int tid, int nthr, int* sh)
{
    int a = 0, b2 = 0, c = 0;
    for (int i = tid; i < m_nwords; i += nthr) {
        unsigned int v = mw[i];
        if (v != 0u && v != 1u && v != 0x3F800000u) a = 1;
        if ((i & 1) ? (v != 0u) : (v > 1u)) b2 = 1;
        unsigned int h0 = v & 0xFFFFu, h1 = v >> 16;
        if (!(h0 == 0u || h0 == 1u || h0 == 0x3F80u || h0 == 0x3C00u)) c = 1;
        if (!(h1 == 0u || h1 == 1u || h1 == 0x3F80u || h1 == 0x3C00u)) c = 1;
    }
    if (a)  sh[0] = 1;
    if (b2) sh[1] = 1;
    if (c)  sh[2] = 1;

    int o = 0, si = 0, nf = 0;
    for (int i = tid; i < s_nwords; i += nthr) {
        unsigned int v = sw[i];
        if ((i & 1) && v != 0u) o = 1;
        if (v >= 1u && v < 0x01000000u) si = 1;
        if (!(v == 0u || (v >= 0x30000000u && v < 0x45000000u))) nf = 1;
    }
    if (o)  sh[3] = 1;
    if (si) sh[4] = 1;
    if (nf) sh[5] = 1;
    __syncthreads();

    int mk;
    if      (!sh[0]) mk = MK_WORD;
    else if (!sh[1]) mk = MK_DWORD;
    else if (!sh[2]) mk = MK_HALF;
    else             mk = MK_BYTE;
    *out_mk = mk;

    int sk;
    if      (!sh[3] && s_nwords >= 2)  sk = SK_I64;
    else if (!sh[5] && !sh[4])         sk = SK_F32;
    else                               sk = SK_I32;
    *out_sk = sk;

    int pad = N;
    if (has_pad) {
        unsigned int p0 = pw[0];
        if (p0 < 0x01000000u) {
            pad = (int)p0;
            if (p0 == 0u) {
                unsigned int p1 = pw[1];
                if (p1 >= 0x3FF00000u && p1 < 0x42000000u)
                    pad = (int)__hiloint2double((int)p1, 0);
            }
        } else {
            float f = __uint_as_float(p0);
            if (f >= 0.0f && f < 16777216.0f) pad = (int)f;
        }
    }
    *out_pad = pad;
}

// ---- prep: per-batch bitmap + C + start (+ CTA0 publishes kinds) ----------
__global__ __launch_bounds__(256)
void prep_kernel(const void* __restrict__ mask,
                 const void* __restrict__ start_idx,
                 const unsigned int* __restrict__ pw, int has_pad,
                 int m_nwords, int s_nwords, int B, int N)
{
    __shared__ int sh[6];
    __shared__ int scnt;
    const int b   = blockIdx.x;
    const int tid = threadIdx.x;
    const int lane = tid & 31;
    const int wid  = tid >> 5;

    if (tid < 6) sh[tid] = 0;
    if (tid == 0) scnt = 0;
    __syncthreads();

    int mk, sk, pad;
    detect_core((const unsigned int*)mask, m_nwords,
                (const unsigned int*)start_idx, s_nwords,
                pw, has_pad, N, &mk, &sk, &pad, tid, 256, sh);

    if (b == 0 && tid == 0) { g_mask_kind = mk; g_start_kind = sk; g_pad = pad; }

    #pragma unroll
    for (int p = 0; p < 4; p++) {
        int col = p * 256 + tid;
        bool vis = true;
        if (col < N) vis = mask_at(mask, mk, b * N + col);
        unsigned int w = __ballot_sync(0xffffffffu, vis);
        if (lane == 0) {
            g_bitmap[b * 32 + p * 8 + wid] = w;
            atomicAdd(&scnt, __popc(~w));
        }
    }
    __syncthreads();

    if (tid == 0) {
        g_C[b] = scnt;
        int s = read_start_k(start_idx, sk, b);
        if (s < 0) s = 0;
        if (s >= N) s = N - 1;
        g_startc[b] = s;
    }
}

// ---- build: one warp per row, asm-batched loads, exact top-K_PREF ---------
__global__ __launch_bounds__(256, 3)
void build_prefix_kernel(const float* __restrict__ dist, int B, int N)
{
    const int gw = blockIdx.x * 8 + (threadIdx.x >> 5);
    if (gw >= B * N) return;
    const int b = gw / N;
    const int r = gw % N;
    const int lane = threadIdx.x & 31;

    unsigned int wr = g_bitmap[b * 32 + (r >> 5)];
    if (((wr >> (r & 31)) & 1u) && r != g_startc[b]) return;

    // per-lane mask bits (elem e=4q+r4, col=4*(lane+32q)+r4); bitmap already
    // has all cols >= N marked visited, so it also covers the load tail.
    unsigned int wl = g_bitmap[b * 32 + lane];
    unsigned int mymask = 0;
    {
        const int shift = (lane & 7) * 4;
        #pragma unroll
        for (int q = 0; q < 8; q++) {
            unsigned int w = __shfl_sync(0xffffffffu, wl, 4 * q + (lane >> 3));
            mymask |= ((w >> shift) & 0xFu) << (4 * q);
        }
    }

    // batched loads FIRST (asm, no interleaved consumers -> MLP=8)
    const float* rp = dist + (size_t)(b * N + r) * N;
    const int nf4 = N >> 2;
    float4 v[8];
    #pragma unroll
    for (int q = 0; q < 8; q++) {
        int f = lane + 32 * q;
        v[q] = (f < nf4) ? ldg128_cs(rp + 4 * f)
                         : make_float4(0.f, 0.f, 0.f, 0.f);
    }

    unsigned int kv[32];
    #pragma unroll
    for (int q = 0; q < 8; q++) {
        const float* pv = (const float*)&v[q];
        #pragma unroll
        for (int r4 = 0; r4 < 4; r4++) {
            int e = 4 * q + r4;
            kv[e] = ((mymask >> e) & 1u) ? 0xFFFFFFFFu : sortable(pv[r4]);
        }
    }

    // per-lane top-2 cache (ascending e, strict < => ties->lowest col)
    unsigned int taken = 0;
    unsigned int b0k = 0xFFFFFFFFu, b1k = 0xFFFFFFFFu;
    int b0e = -1, b1e = -1;
    #pragma unroll
    for (int e = 0; e < 32; e++) {
        unsigned int k = kv[e];
        if (k < b0k)      { b1k = b0k; b1e = b0e; b0k = k; b0e = e; }
        else if (k < b1k) { b1k = k;   b1e = e; }
    }

    unsigned int res = 0xFFFFu;
    for (int it = 0; it < K_PREF; it++) {
        unsigned int wmin = __reduce_min_sync(0xffffffffu, b0k);
        if (wmin == 0xFFFFFFFFu) break;
        unsigned int mycol = 0xFFFFFFFFu;
        if (b0k == wmin)
            mycol = 4u * (unsigned)(lane + 32 * (b0e >> 2)) + (unsigned)(b0e & 3);
        unsigned int cmin = __reduce_min_sync(0xffffffffu, mycol);
        if (lane == it) res = cmin;

        if (((cmin >> 2) & 31u) == (unsigned)lane) {
            int e = (int)(((cmin >> 7) << 2) | (cmin & 3u));
            taken |= 1u << e;
            if (b1e >= 0) { b0k = b1k; b0e = b1e; b1e = -1; b1k = 0xFFFFFFFFu; }
            else {
                b0k = 0xFFFFFFFFu; b0e = -1; b1k = 0xFFFFFFFFu; b1e = -1;
                #pragma unroll
                for (int e2 = 0; e2 < 32; e2++) {
                    unsigned int k = ((taken >> e2) & 1u) ? 0xFFFFFFFFu : kv[e2];
                    if (k < b0k)      { b1k = b0k; b1e = b0e; b0k = k; b0e = e2; }
                    else if (k < b1k) { b1k = k;   b1e = e2; }
                }
            }
        }
    }
    if (lane < K_PREF)
        g_prefix[(size_t)gw * K_PREF + lane] = (unsigned short)res;
}

// ---- chain: prefix in SMEM, bitmap in warp-0 registers --------------------
__global__ __launch_bounds__(128, 1)
void greedy_prefix_kernel(const float* __restrict__ dist,
                          float* __restrict__ out,
                          int B, int N, int write_len)
{
    __shared__ unsigned short s_pref[1024 * K_PREF];   // 32KB

    const int b    = blockIdx.x;
    const int tid  = threadIdx.x;
    const int lane = tid & 31;
    const int wid  = tid >> 5;

    {
        const uint4* src = (const uint4*)(g_prefix + (size_t)b * N * K_PREF);
        uint4* dst4 = (uint4*)s_pref;
        const int nvec = 2 * N;
        for (int i = tid; i < nvec; i += 128) dst4[i] = src[i];
    }
    __syncthreads();
    if (wid != 0) return;

    unsigned int word = g_bitmap[b * 32 + lane];
    const int C = g_C[b];
    int point = g_startc[b];

    const float* dbase = dist + (size_t)b * N * N;
    float* pred = out + (size_t)b * N;
    const float padf = (float)g_pad;

    for (int t = 0; t < C; t++) {
        unsigned int c = 0xFFFFu;
        if (lane < K_PREF) c = s_pref[point * K_PREF + lane];
        unsigned int w = __shfl_sync(0xffffffffu, word, (int)((c >> 5) & 31u));
        bool ok = (c < (unsigned)N) && !((w >> (c & 31u)) & 1u);
        unsigned int bal = __ballot_sync(0xffffffffu, ok);

        unsigned int colstar;
        if (bal) {
            // lowest set lane == lowest prefix rank (only lanes<16 can be ok)
            colstar = __shfl_sync(0xffffffffu, c, __ffs(bal) - 1);
        } else {
            const float* rp = dbase + (size_t)point * N;
            unsigned int bb = 0xFFFFFFFFu, bc = 0;
            #pragma unroll
            for (int q = 0; q < 8; q++) {
                int base = 32 * lane + 4 * q;
                if (base + 3 < N) {
                    float4 v = __ldg((const float4*)(rp + base));
                    const float* pv = (const float*)&v;
                    #pragma unroll
                    for (int r4 = 0; r4 < 4; r4++) {
                        if (!((word >> (4 * q + r4)) & 1u)) {
                            unsigned int sk = sortable(pv[r4]);
                            if (sk < bb) { bb = sk; bc = (unsigned)(base + r4); }
                        }
                    }
                }
            }
            unsigned int wm = __reduce_min_sync(0xffffffffu, bb);
            colstar = __reduce_min_sync(0xffffffffu,
                                        (bb == wm) ? bc : 0xFFFFFFFFu);
        }

        if (lane == 0) pred[t] = (float)colstar;
        if ((colstar >> 5) == (unsigned)lane) word |= 1u << (colstar & 31u);
        point = (int)colstar;
    }

    for (int t = C + lane; t < N; t += 32) pred[t] = padf;
    if (write_len && lane == 0) out[(size_t)B * N + b] = (float)C;
}

// ======== fallback path (non-conforming shapes): proven f32 chain ==========
__global__ void detect_kernel(const unsigned int* __restrict__ mw, int m_nwords,
                              const unsigned int* __restrict__ sw, int s_nwords,
                              const unsigned int* __restrict__ pw, int has_pad,
                              int N)
{
    __shared__ int sh[6];
    if (threadIdx.x < 6) sh[threadIdx.x] = 0;
    __syncthreads();
    int mk, sk, pad;
    detect_core(mw, m_nwords, sw, s_nwords, pw, has_pad, N,
                &mk, &sk, &pad, threadIdx.x, blockDim.x, sh);
    if (threadIdx.x == 0) { g_mask_kind = mk; g_start_kind = sk; g_pad = pad; }
}

__device__ __forceinline__ float4 ldg128_nc(const float* p) {
    float4 v;
    asm volatile("ld.global.nc.v4.f32 {%0,%1,%2,%3}, [%4];"
                 : "=f"(v.x), "=f"(v.y), "=f"(v.z), "=f"(v.w)
                 : "l"(p));
    return v;
}

__global__ __launch_bounds__(128, 1)
void greedy_f32_kernel(const float* __restrict__ dist,
                       const void*  __restrict__ mask,
                       const void*  __restrict__ start_idx,
                       float*       __restrict__ out,
                       int B, int N, int write_len)
{
    __shared__ unsigned long long sbuf[2][4];
    __shared__ int scnt[4];

    const int b    = blockIdx.x;
    const int tid  = threadIdx.x;
    const int lane = tid & 31;
    const int wid  = tid >> 5;
    const int mk   = g_mask_kind;
    const float padf = (float)g_pad;
    const int nf4  = N >> 2;
    const unsigned int BIGBITS = 0x49742400u;

    const bool v0 = (tid       < nf4);
    const bool v1 = (tid + 128 < nf4);

    unsigned int m = 0;
    #pragma unroll
    for (int s = 0; s < 2; s++) {
        #pragma unroll
        for (int r = 0; r < 4; r++) {
            int col = 4 * (tid + 128 * s) + r;
            bool mb = true;
            if (col < N) mb = mask_at(mask, mk, b * N + col);
            if (mb) m |= 1u << (s * 4 + r);
        }
    }

    {
        unsigned int cnt = 8u - (unsigned)__popc(m);
        cnt = __reduce_add_sync(0xffffffffu, cnt);
        if (lane == 0) scnt[wid] = (int)cnt;
    }
    __syncthreads();
    const int C = scnt[0] + scnt[1] + scnt[2] + scnt[3];

    int point = read_start_k(start_idx, g_start_kind, b);
    if (point < 0) point = 0;
    if (point >= N) point = N - 1;

    const float* dbase = dist + (size_t)b * N * N;
    float* pred = out + (size_t)b * N;

    for (int t = 0; t < C; t++) {
        const float* rp = dbase + (size_t)point * N;

        float4 a = v0 ? ldg128_nc(rp + 4 * tid)
                      : make_float4(1e6f, 1e6f, 1e6f, 1e6f);
        float4 c = v1 ? ldg128_nc(rp + 4 * (tid + 128))
                      : make_float4(1e6f, 1e6f, 1e6f, 1e6f);

        unsigned int bb = BIGBITS, bc = 0;
        const float* pa = (const float*)&a;
        const float* pc = (const float*)&c;
        #pragma unroll
        for (int r = 0; r < 4; r++) {
            unsigned int fb = ((m >> r) & 1u) ? BIGBITS : __float_as_uint(pa[r]);
            if (fb < bb) { bb = fb; bc = 4 * tid + r; }
        }
        #pragma unroll
        for (int r = 0; r < 4; r++) {
            unsigned int fb = ((m >> (4 + r)) & 1u) ? BIGBITS : __float_as_uint(pc[r]);
            if (fb < bb) { bb = fb; bc = 4 * (tid + 128) + r; }
        }

        unsigned int wmin = __reduce_min_sync(0xffffffffu, bb);
        unsigned int colc = (bb == wmin) ? bc : 0xFFFFFFFFu;
        unsigned int wcol = __reduce_min_sync(0xffffffffu, colc);

        if (lane == 0)
            sbuf[t & 1][wid] = ((unsigned long long)wmin << 32) | wcol;
        __syncthreads();
        unsigned long long k0 = sbuf[t & 1][0], k1 = sbuf[t & 1][1];
        unsigned long long k2 = sbuf[t & 1][2], k3 = sbuf[t & 1][3];
        unsigned long long ka = k0 < k1 ? k0 : k1;
        unsigned long long kb = k2 < k3 ? k2 : k3;
        unsigned long long k  = ka < kb ? ka : kb;

        int idx = (int)(unsigned int)k;
        if (tid == 0) pred[t] = (float)idx;

        int f = idx >> 2;
        if ((f & 127) == tid)
            m |= 1u << (((f >> 7) << 2) | (idx & 3));
        point = idx;
    }

    for (int t = C + tid; t < N; t += 128) pred[t] = padf;
    if (write_len && tid == 0) out[(size_t)B * N + b] = (float)C;
}

extern "C" void kernel_launch(void* const* d_in, const int* in_sizes, int n_in,
                              void* d_out, int out_size)
{
    // identify inputs by element count (order-proof)
    int di = 0, mi = -1, si = -1, pi = -1;
    for (int i = 1; i < n_in; i++)
        if (in_sizes[i] > in_sizes[di]) di = i;
    for (int i = 0; i < n_in; i++) {
        if (i == di) continue;
        if (pi < 0 || in_sizes[i] < in_sizes[pi]) pi = i;
    }
    for (int i = 0; i < n_in; i++) {
        if (i == di || i == pi) continue;
        if (mi < 0) { mi = i; continue; }
        si = i;
    }
    if (si >= 0 && in_sizes[si] > in_sizes[mi]) { int t = mi; mi = si; si = t; }
    if (si < 0) { si = pi; pi = -1; }

    const float* dist  = (const float*)d_in[di];
    const void*  mask  = d_in[mi];
    const void*  start = d_in[si];
    const void*  padp  = (pi >= 0) ? d_in[pi] : nullptr;

    const int B = in_sizes[si];
    const int N = in_sizes[mi] / B;

    int m_nwords = in_sizes[mi] / 4;
    if (m_nwords > 2048) m_nwords = 2048;
    int s_nwords = in_sizes[si];

    int write_len = (out_size >= B * N + B) ? 1 : 0;

    bool fast_ok = (N % 4 == 0) && (N >= 4) && (N <= 1024) && (B <= MAXB) &&
                   ((long long)B * N <= 16777216LL / K_PREF);
    if (fast_ok) {
        prep_kernel<<<B, 256>>>(mask, start,
                                padp ? (const unsigned int*)padp
                                     : (const unsigned int*)start,
                                padp ? 1 : 0, m_nwords, s_nwords, B, N);
        build_prefix_kernel<<<(B * N + 7) / 8, 256>>>(dist, B, N);
        greedy_prefix_kernel<<<B, 128>>>(dist, (float*)d_out, B, N, write_len);
    } else {
        detect_kernel<<<1, 256>>>((const unsigned int*)mask, m_nwords,
                                  (const unsigned int*)start, s_nwords,
                                  padp ? (const unsigned int*)padp
                                       : (const unsigned int*)start,
                                  padp ? 1 : 0, N);
        greedy_f32_kernel<<<B, 128>>>(dist, mask, start, (float*)d_out,
                                      B, N, write_len);
    }
}

// round 17
// speedup vs baseline: 1.1424x; 1.1424x over previous
#include <cuda_runtime.h>
#include <cstdint>

// ---------------------------------------------------------------------------
// Batched greedy nearest-neighbor (B=64, N=1000).
// prep:  per-batch visited bitmap (ballot), C, clamped start, dtype detect.
// build: one warp per reachable row; 8 asm-batched LDG.128.cs (MLP=8), exact
//        top-16 cols in (sortable-f32,col) order. __launch_bounds__(256,2).
// chain: prefix in SMEM, visited bitmap in warp registers; step = LDS +
//        SHFL + BALLOT/FFS + SHFL; prefix-exhausted -> exact full-row scan
//        with asm-batched loads (clamped tail; bitmap masks tail cols).
// Non-conforming shapes -> proven direct-f32 chain.
// (Identical to R15 submission; R15 was a broker/container failure.)
// ---------------------------------------------------------------------------

#define MK_BYTE  0
#define MK_WORD  1
#define MK_DWORD 2
#define MK_HALF  3

#define SK_I32 0
#define SK_I64 1
#define SK_F32 2

#define K_PREF 16
#define MAXB   65536

__device__ int g_mask_kind, g_start_kind, g_pad;
__device__ unsigned short g_prefix[16777216];      // 32MB (<=1M rows)
__device__ unsigned int   g_bitmap[MAXB * 32];     // 8MB  per-batch visited
__device__ int            g_startc[MAXB];
__device__ int            g_C[MAXB];

__device__ __forceinline__ bool mask_at(const void* mask, int mk, int off) {
    if (mk == MK_WORD)  return ((const unsigned int*)mask)[off]      != 0u;
    if (mk == MK_BYTE)  return ((const unsigned char*)mask)[off]     != 0u;
    if (mk == MK_HALF)  return ((const unsigned short*)mask)[off]    != 0u;
    return ((const unsigned int*)mask)[2 * off] != 0u;                 // i64
}

__device__ __forceinline__ int read_start_k(const void* start_idx, int sk, int b) {
    const int* s32 = (const int*)start_idx;
    if (sk == SK_I64) return s32[2 * b];
    if (sk == SK_F32) return (int)((const float*)start_idx)[b];
    return s32[b];
}

__device__ __forceinline__ unsigned int sortable(float f) {
    unsigned int fb = __float_as_uint(f);
    return fb ^ ((((int)fb) >> 31) | 0x80000000u);
}

__device__ __forceinline__ float4 ldg128_cs(const float* p) {
    float4 v;
    asm volatile("ld.global.cs.v4.f32 {%0,%1,%2,%3}, [%4];"
                 : "=f"(v.x), "=f"(v.y), "=f"(v.z), "=f"(v.w)
                 : "l"(p));
    return v;
}

__device__ __forceinline__ float4 ldg128_nc(const float* p) {
    float4 v;
    asm volatile("ld.global.nc.v4.f32 {%0,%1,%2,%3}, [%4];"
                 : "=f"(v.x), "=f"(v.y), "=f"(v.z), "=f"(v.w)
                 : "l"(p));
    return v;
}

// detection core, shared by prep (per-CTA) and detect_kernel
__device__ void detect_core(const unsigned int* mw, int m_nwords,
                            const unsigned int* sw, int s_nwords,
                            const unsigned int* pw, int has_pad, int N,
                            int* out_mk, int* out_sk, int* out_pad,
                            int tid, int nthr, int* sh)
{
    int a = 0, b2 = 0, c = 0;
    for (int i = tid; i < m_nwords; i += nthr) {
        unsigned int v = mw[i];
        if (v != 0u && v != 1u && v != 0x3F800000u) a = 1;
        if ((i & 1) ? (v != 0u) : (v > 1u)) b2 = 1;
        unsigned int h0 = v & 0xFFFFu, h1 = v >> 16;
        if (!(h0 == 0u || h0 == 1u || h0 == 0x3F80u || h0 == 0x3C00u)) c = 1;
        if (!(h1 == 0u || h1 == 1u || h1 == 0x3F80u || h1 == 0x3C00u)) c = 1;
    }
    if (a)  sh[0] = 1;
    if (b2) sh[1] = 1;
    if (c)  sh[2] = 1;

    int o = 0, si = 0, nf = 0;
    for (int i = tid; i < s_nwords; i += nthr) {
        unsigned int v = sw[i];
        if ((i & 1) && v != 0u) o = 1;
        if (v >= 1u && v < 0x01000000u) si = 1;
        if (!(v == 0u || (v >= 0x30000000u && v < 0x45000000u))) nf = 1;
    }
    if (o)  sh[3] = 1;
    if (si) sh[4] = 1;
    if (nf) sh[5] = 1;
    __syncthreads();

    int mk;
    if      (!sh[0]) mk = MK_WORD;
    else if (!sh[1]) mk = MK_DWORD;
    else if (!sh[2]) mk = MK_HALF;
    else             mk = MK_BYTE;
    *out_mk = mk;

    int sk;
    if      (!sh[3] && s_nwords >= 2)  sk = SK_I64;
    else if (!sh[5] && !sh[4])         sk = SK_F32;
    else                               sk = SK_I32;
    *out_sk = sk;

    int pad = N;
    if (has_pad) {
        unsigned int p0 = pw[0];
        if (p0 < 0x01000000u) {
            pad = (int)p0;
            if (p0 == 0u) {
                unsigned int p1 = pw[1];
                if (p1 >= 0x3FF00000u && p1 < 0x42000000u)
                    pad = (int)__hiloint2double((int)p1, 0);
            }
        } else {
            float f = __uint_as_float(p0);
            if (f >= 0.0f && f < 16777216.0f) pad = (int)f;
        }
    }
    *out_pad = pad;
}

// ---- prep: per-batch bitmap + C + start (+ CTA0 publishes kinds) ----------
__global__ __launch_bounds__(256)
void prep_kernel(const void* __restrict__ mask,
                 const void* __restrict__ start_idx,
                 const unsigned int* __restrict__ pw, int has_pad,
                 int m_nwords, int s_nwords, int B, int N)
{
    __shared__ int sh[6];
    __shared__ int scnt;
    const int b   = blockIdx.x;
    const int tid = threadIdx.x;
    const int lane = tid & 31;
    const int wid  = tid >> 5;

    if (tid < 6) sh[tid] = 0;
    if (tid == 0) scnt = 0;
    __syncthreads();

    int mk, sk, pad;
    detect_core((const unsigned int*)mask, m_nwords,
                (const unsigned int*)start_idx, s_nwords,
                pw, has_pad, N, &mk, &sk, &pad, tid, 256, sh);

    if (b == 0 && tid == 0) { g_mask_kind = mk; g_start_kind = sk; g_pad = pad; }

    #pragma unroll
    for (int p = 0; p < 4; p++) {
        int col = p * 256 + tid;
        bool vis = true;
        if (col < N) vis = mask_at(mask, mk, b * N + col);
        unsigned int w = __ballot_sync(0xffffffffu, vis);
        if (lane == 0) {
            g_bitmap[b * 32 + p * 8 + wid] = w;
            atomicAdd(&scnt, __popc(~w));
        }
    }
    __syncthreads();

    if (tid == 0) {
        g_C[b] = scnt;
        int s = read_start_k(start_idx, sk, b);
        if (s < 0) s = 0;
        if (s >= N) s = N - 1;
        g_startc[b] = s;
    }
}

// ---- build: one warp per row, asm-batched loads, exact top-K_PREF ---------
__global__ __launch_bounds__(256, 2)
void build_prefix_kernel(const float* __restrict__ dist, int B, int N)
{
    const int gw = blockIdx.x * 8 + (threadIdx.x >> 5);
    if (gw >= B * N) return;
    const int b = gw / N;
    const int r = gw % N;
    const int lane = threadIdx.x & 31;

    unsigned int wr = g_bitmap[b * 32 + (r >> 5)];
    if (((wr >> (r & 31)) & 1u) && r != g_startc[b]) return;

    unsigned int wl = g_bitmap[b * 32 + lane];
    unsigned int mymask = 0;
    {
        const int shift = (lane & 7) * 4;
        #pragma unroll
        for (int q = 0; q < 8; q++) {
            unsigned int w = __shfl_sync(0xffffffffu, wl, 4 * q + (lane >> 3));
            mymask |= ((w >> shift) & 0xFu) << (4 * q);
        }
    }

    const float* rp = dist + (size_t)(b * N + r) * N;
    const int nf4 = N >> 2;
    float4 v[8];
    #pragma unroll
    for (int q = 0; q < 8; q++) {
        int f = lane + 32 * q;
        int fc = (f < nf4) ? f : (nf4 - 1);        // clamp; mask kills tail
        v[q] = ldg128_cs(rp + 4 * fc);
    }

    unsigned int kv[32];
    #pragma unroll
    for (int q = 0; q < 8; q++) {
        const float* pv = (const float*)&v[q];
        #pragma unroll
        for (int r4 = 0; r4 < 4; r4++) {
            int e = 4 * q + r4;
            kv[e] = ((mymask >> e) & 1u) ? 0xFFFFFFFFu : sortable(pv[r4]);
        }
    }

    unsigned int taken = 0;
    unsigned int b0k = 0xFFFFFFFFu, b1k = 0xFFFFFFFFu;
    int b0e = -1, b1e = -1;
    #pragma unroll
    for (int e = 0; e < 32; e++) {
        unsigned int k = kv[e];
        if (k < b0k)      { b1k = b0k; b1e = b0e; b0k = k; b0e = e; }
        else if (k < b1k) { b1k = k;   b1e = e; }
    }

    unsigned int res = 0xFFFFu;
    for (int it = 0; it < K_PREF; it++) {
        unsigned int wmin = __reduce_min_sync(0xffffffffu, b0k);
        if (wmin == 0xFFFFFFFFu) break;
        unsigned int mycol = 0xFFFFFFFFu;
        if (b0k == wmin)
            mycol = 4u * (unsigned)(lane + 32 * (b0e >> 2)) + (unsigned)(b0e & 3);
        unsigned int cmin = __reduce_min_sync(0xffffffffu, mycol);
        if (lane == it) res = cmin;

        if (((cmin >> 2) & 31u) == (unsigned)lane) {
            int e = (int)(((cmin >> 7) << 2) | (cmin & 3u));
            taken |= 1u << e;
            if (b1e >= 0) { b0k = b1k; b0e = b1e; b1e = -1; b1k = 0xFFFFFFFFu; }
            else {
                b0k = 0xFFFFFFFFu; b0e = -1; b1k = 0xFFFFFFFFu; b1e = -1;
                #pragma unroll
                for (int e2 = 0; e2 < 32; e2++) {
                    unsigned int k = ((taken >> e2) & 1u) ? 0xFFFFFFFFu : kv[e2];
                    if (k < b0k)      { b1k = b0k; b1e = b0e; b0k = k; b0e = e2; }
                    else if (k < b1k) { b1k = k;   b1e = e2; }
                }
            }
        }
    }
    if (lane < K_PREF)
        g_prefix[(size_t)gw * K_PREF + lane] = (unsigned short)res;
}

// ---- chain: prefix in SMEM, bitmap in warp-0 registers --------------------
__global__ __launch_bounds__(128, 1)
void greedy_prefix_kernel(const float* __restrict__ dist,
                          float* __restrict__ out,
                          int B, int N, int write_len)
{
    __shared__ unsigned short s_pref[1024 * K_PREF];   // 32KB

    const int b    = blockIdx.x;
    const int tid  = threadIdx.x;
    const int lane = tid & 31;
    const int wid  = tid >> 5;

    {
        const uint4* src = (const uint4*)(g_prefix + (size_t)b * N * K_PREF);
        uint4* dst4 = (uint4*)s_pref;
        const int nvec = 2 * N;
        for (int i = tid; i < nvec; i += 128) dst4[i] = src[i];
    }
    __syncthreads();
    if (wid != 0) return;

    unsigned int word = g_bitmap[b * 32 + lane];
    const int C = g_C[b];
    int point = g_startc[b];

    const float* dbase = dist + (size_t)b * N * N;
    float* pred = out + (size_t)b * N;
    const float padf = (float)g_pad;
    const int nf4 = N >> 2;

    for (int t = 0; t < C; t++) {
        unsigned int c = 0xFFFFu;
        if (lane < K_PREF) c = s_pref[point * K_PREF + lane];
        unsigned int w = __shfl_sync(0xffffffffu, word, (int)((c >> 5) & 31u));
        bool ok = (c < (unsigned)N) && !((w >> (c & 31u)) & 1u);
        unsigned int bal = __ballot_sync(0xffffffffu, ok);

        unsigned int colstar;
        if (bal) {
            colstar = __shfl_sync(0xffffffffu, c, __ffs(bal) - 1);
        } else {
            const float* rp = dbase + (size_t)point * N;
            float4 vv[8];
            #pragma unroll
            for (int q = 0; q < 8; q++) {
                int f = 8 * lane + q;               // col = 4*f ... 4*f+3
                int fc = (f < nf4) ? f : (nf4 - 1);
                vv[q] = ldg128_nc(rp + 4 * fc);
            }
            unsigned int bb = 0xFFFFFFFFu, bc = 0;
            #pragma unroll
            for (int q = 0; q < 8; q++) {
                const float* pv = (const float*)&vv[q];
                #pragma unroll
                for (int r4 = 0; r4 < 4; r4++) {
                    int j = 4 * q + r4;
                    if (!((word >> j) & 1u)) {
                        unsigned int sk = sortable(pv[r4]);
                        if (sk < bb) { bb = sk; bc = (unsigned)(32 * lane + j); }
                    }
                }
            }
            unsigned int wm = __reduce_min_sync(0xffffffffu, bb);
            colstar = __reduce_min_sync(0xffffffffu,
                                        (bb == wm) ? bc : 0xFFFFFFFFu);
        }

        if (lane == 0) pred[t] = (float)colstar;
        if ((colstar >> 5) == (unsigned)lane) word |= 1u << (colstar & 31u);
        point = (int)colstar;
    }

    for (int t = C + lane; t < N; t += 32) pred[t] = padf;
    if (write_len && lane == 0) out[(size_t)B * N + b] = (float)C;
}

// ======== fallback path (non-conforming shapes): proven f32 chain ==========
__global__ void detect_kernel(const unsigned int* __restrict__ mw, int m_nwords,
                              const unsigned int* __restrict__ sw, int s_nwords,
                              const unsigned int* __restrict__ pw, int has_pad,
                              int N)
{
    __shared__ int sh[6];
    if (threadIdx.x < 6) sh[threadIdx.x] = 0;
    __syncthreads();
    int mk, sk, pad;
    detect_core(mw, m_nwords, sw, s_nwords, pw, has_pad, N,
                &mk, &sk, &pad, threadIdx.x, blockDim.x, sh);
    if (threadIdx.x == 0) { g_mask_kind = mk; g_start_kind = sk; g_pad = pad; }
}

__global__ __launch_bounds__(128, 1)
void greedy_f32_kernel(const float* __restrict__ dist,
                       const void*  __restrict__ mask,
                       const void*  __restrict__ start_idx,
                       float*       __restrict__ out,
                       int B, int N, int write_len)
{
    __shared__ unsigned long long sbuf[2][4];
    __shared__ int scnt[4];

    const int b    = blockIdx.x;
    const int tid  = threadIdx.x;
    const int lane = tid & 31;
    const int wid  = tid >> 5;
    const int mk   = g_mask_kind;
    const float padf = (float)g_pad;
    const int nf4  = N >> 2;
    const unsigned int BIGBITS = 0x49742400u;

    const bool v0 = (tid       < nf4);
    const bool v1 = (tid + 128 < nf4);

    unsigned int m = 0;
    #pragma unroll
    for (int s = 0; s < 2; s++) {
        #pragma unroll
        for (int r = 0; r < 4; r++) {
            int col = 4 * (tid + 128 * s) + r;
            bool mb = true;
            if (col < N) mb = mask_at(mask, mk, b * N + col);
            if (mb) m |= 1u << (s * 4 + r);
        }
    }

    {
        unsigned int cnt = 8u - (unsigned)__popc(m);
        cnt = __reduce_add_sync(0xffffffffu, cnt);
        if (lane == 0) scnt[wid] = (int)cnt;
    }
    __syncthreads();
    const int C = scnt[0] + scnt[1] + scnt[2] + scnt[3];

    int point = read_start_k(start_idx, g_start_kind, b);
    if (point < 0) point = 0;
    if (point >= N) point = N - 1;

    const float* dbase = dist + (size_t)b * N * N;
    float* pred = out + (size_t)b * N;

    for (int t = 0; t < C; t++) {
        const float* rp = dbase + (size_t)point * N;

        float4 a = v0 ? ldg128_nc(rp + 4 * tid)
                      : make_float4(1e6f, 1e6f, 1e6f, 1e6f);
        float4 c = v1 ? ldg128_nc(rp + 4 * (tid + 128))
                      : make_float4(1e6f, 1e6f, 1e6f, 1e6f);

        unsigned int bb = BIGBITS, bc = 0;
        const float* pa = (const float*)&a;
        const float* pc = (const float*)&c;
        #pragma unroll
        for (int r = 0; r < 4; r++) {
            unsigned int fb = ((m >> r) & 1u) ? BIGBITS : __float_as_uint(pa[r]);
            if (fb < bb) { bb = fb; bc = 4 * tid + r; }
        }
        #pragma unroll
        for (int r = 0; r < 4; r++) {
            unsigned int fb = ((m >> (4 + r)) & 1u) ? BIGBITS : __float_as_uint(pc[r]);
            if (fb < bb) { bb = fb; bc = 4 * (tid + 128) + r; }
        }

        unsigned int wmin = __reduce_min_sync(0xffffffffu, bb);
        unsigned int colc = (bb == wmin) ? bc : 0xFFFFFFFFu;
        unsigned int wcol = __reduce_min_sync(0xffffffffu, colc);

        if (lane == 0)
            sbuf[t & 1][wid] = ((unsigned long long)wmin << 32) | wcol;
        __syncthreads();
        unsigned long long k0 = sbuf[t & 1][0], k1 = sbuf[t & 1][1];
        unsigned long long k2 = sbuf[t & 1][2], k3 = sbuf[t & 1][3];
        unsigned long long ka = k0 < k1 ? k0 : k1;
        unsigned long long kb = k2 < k3 ? k2 : k3;
        unsigned long long k  = ka < kb ? ka : kb;

        int idx = (int)(unsigned int)k;
        if (tid == 0) pred[t] = (float)idx;

        int f = idx >> 2;
        if ((f & 127) == tid)
            m |= 1u << (((f >> 7) << 2) | (idx & 3));
        point = idx;
    }

    for (int t = C + tid; t < N; t += 128) pred[t] = padf;
    if (write_len && tid == 0) out[(size_t)B * N + b] = (float)C;
}

extern "C" void kernel_launch(void* const* d_in, const int* in_sizes, int n_in,
                              void* d_out, int out_size)
{
    // identify inputs by element count (order-proof)
    int di = 0, mi = -1, si = -1, pi = -1;
    for (int i = 1; i < n_in; i++)
        if (in_sizes[i] > in_sizes[di]) di = i;
    for (int i = 0; i < n_in; i++) {
        if (i == di) continue;
        if (pi < 0 || in_sizes[i] < in_sizes[pi]) pi = i;
    }
    for (int i = 0; i < n_in; i++) {
        if (i == di || i == pi) continue;
        if (mi < 0) { mi = i; continue; }
        si = i;
    }
    if (si >= 0 && in_sizes[si] > in_sizes[mi]) { int t = mi; mi = si; si = t; }
    if (si < 0) { si = pi; pi = -1; }

    const float* dist  = (const float*)d_in[di];
    const void*  mask  = d_in[mi];
    const void*  start = d_in[si];
    const void*  padp  = (pi >= 0) ? d_in[pi] : nullptr;

    const int B = in_sizes[si];
    const int N = in_sizes[mi] / B;

    int m_nwords = in_sizes[mi] / 4;
    if (m_nwords > 2048) m_nwords = 2048;
    int s_nwords = in_sizes[si];

    int write_len = (out_size >= B * N + B) ? 1 : 0;

    bool fast_ok = (N % 4 == 0) && (N >= 4) && (N <= 1024) && (B <= MAXB) &&
                   ((long long)B * N <= 16777216LL / K_PREF);
    if (fast_ok) {
        prep_kernel<<<B, 256>>>(mask, start,
                                padp ? (const unsigned int*)padp
                                     : (const unsigned int*)start,
                                padp ? 1 : 0, m_nwords, s_nwords, B, N);
        build_prefix_kernel<<<(B * N + 7) / 8, 256>>>(dist, B, N);
        greedy_prefix_kernel<<<B, 128>>>(dist, (float*)d_out, B, N, write_len);
    } else {
        detect_kernel<<<1, 256>>>((const unsigned int*)mask, m_nwords,
                                  (const unsigned int*)start, s_nwords,
                                  padp ? (const unsigned int*)padp
                                       : (const unsigned int*)start,
                                  padp ? 1 : 0, N);
        greedy_f32_kernel<<<B, 128>>>(dist, mask, start, (float*)d_out,
                                      B, N, write_len);
    }
}